// round 5
// baseline (speedup 1.0000x reference)
#include <cuda_runtime.h>
#include <cstdint>

// Problem constants (B=4, S=1024, K=32, V=32000)
#define BB 4
#define SS 1024
#define KK 32
#define VV 32000
#define ROWS (BB * SS)            // 4096
#define NCHUNK 8
#define CHUNK_F  (VV / NCHUNK)    // 4000 floats per chunk
#define CHUNK_F4 (CHUNK_F / 4)    // 1000 float4 per chunk

// Scratch (device globals — no allocation).
__device__ float g_probs[ROWS * KK];
__device__ int   g_tgt  [ROWS * KK];
__device__ int   g_flag [ROWS];     // 0 -> probs not ready; 1 -> ready

__device__ __forceinline__ float fast_tanh(float x) {
    float r;
    asm("tanh.approx.f32 %0, %1;" : "=f"(r) : "f"(x));
    return r;
}

// ---------------------------------------------------------------------------
// Single fused kernel. Grid (NCHUNK, ROWS), 256 threads.
//  - every block zeroes its 4000-float chunk of one row (flat write shape)
//  - chunk-0 blocks: warp 0 computes the row's combiner (live subgraph:
//    label_counts->fc2->tempe ; log feats->fc1->noise ; softmax), dedups
//    duplicate targets in-warp, publishes (t,p) + release flag, and scatters
//    targets landing in chunk 0.
//  - chunk 1..7 blocks: after zeroing + __syncthreads, warp 0 acquires the
//    row flag (spin; producer precedes consumer in CTA dispatch order) and
//    scatters targets landing in its chunk with plain stores (dedup done).
// ---------------------------------------------------------------------------
__global__ void __launch_bounds__(256) fused_kernel(
    const int*   __restrict__ tgt,
    const float* __restrict__ dists,
    const float* __restrict__ kkf,
    const float* __restrict__ nsp,
    const float* __restrict__ fc1_w1,  // (2,4)
    const float* __restrict__ fc1_b1,  // (4)
    const float* __restrict__ fc1_w2,  // (4,1)
    const float* __restrict__ fc1_b2,  // (1)
    const float* __restrict__ fc2_w1,  // (64,32)
    const float* __restrict__ fc2_b1,  // (32)
    const float* __restrict__ fc2_w2,  // (32,2)
    const float* __restrict__ fc2_b2,  // (2)
    float*       __restrict__ out)     // (ROWS, VV)
{
    const unsigned FULL = 0xffffffffu;
    const int row   = blockIdx.y;
    const int chunk = blockIdx.x;
    const int tid   = threadIdx.x;
    const int lane  = tid & 31;

    const int lo = chunk * CHUNK_F;
    float* rowp = out + (size_t)row * VV + lo;
    float4* rowp4 = (float4*)rowp;
    const float4 z = make_float4(0.f, 0.f, 0.f, 0.f);

    if (chunk == 0 && tid < 32) {
        // ============ warp 0 of chunk-0 block: combiner math ==============
        int   base = row * KK + lane;
        int   t    = tgt[base];
        float d    = dists[base];
        float lkf  = __logf(kkf[base]);
        float lsp  = __logf(nsp[base]);

        // label_counts: distinct nonzero labels in prefix [0..lane]
        int fo = (t != 0) ? 1 : 0;
        #pragma unroll
        for (int j = 0; j < 31; j++) {
            int tj = __shfl_sync(FULL, t, j);
            if (j < lane && tj == t) fo = 0;
        }
        float lc = (float)fo;
        #pragma unroll
        for (int off = 1; off < 32; off <<= 1) {
            float v = __shfl_up_sync(FULL, lc, off);
            if (lane >= off) lc += v;
        }

        // fc1 -> noise_logit
        float noise = fc1_b2[0];
        #pragma unroll
        for (int m = 0; m < 4; m++) {
            float h = fmaf(lkf, fc1_w1[m], fmaf(lsp, fc1_w1[4 + m], fc1_b1[m]));
            noise = fmaf(fast_tanh(h), fc1_w2[m], noise);
        }

        // fc2: hidden[lane] = b1[lane] + sum_j feat[j]*W1[j][lane]
        float hid = fc2_b1[lane];
        #pragma unroll
        for (int j = 0; j < 32; j++) {
            float fj = __shfl_sync(FULL, d, j);
            hid = fmaf(fj, fc2_w1[j * 32 + lane], hid);
        }
        #pragma unroll
        for (int j = 0; j < 32; j++) {
            float fj = __shfl_sync(FULL, lc, j);
            hid = fmaf(fj, fc2_w1[(32 + j) * 32 + lane], hid);
        }
        float ht = fast_tanh(hid);

        // lambda_logit[1] -> tempe
        float l1 = ht * fc2_w2[lane * 2 + 1];
        #pragma unroll
        for (int off = 16; off; off >>= 1) l1 += __shfl_xor_sync(FULL, l1, off);
        l1 += fc2_b2[1];
        float tempe = 1.f / (1.f + __expf(-l1));

        // softmax over K of (-d*tempe + noise)
        float logit = fmaf(-d, tempe, noise);
        float mx = logit;
        #pragma unroll
        for (int off = 16; off; off >>= 1) mx = fmaxf(mx, __shfl_xor_sync(FULL, mx, off));
        float e = __expf(logit - mx);
        float s = e;
        #pragma unroll
        for (int off = 16; off; off >>= 1) s += __shfl_xor_sync(FULL, s, off);
        float p = e / s;

        // in-warp duplicate-target combine: keep first occurrence, sum p
        float psum = 0.f;
        int firstl = 32;
        #pragma unroll
        for (int j = 0; j < 32; j++) {
            int   tj = __shfl_sync(FULL, t, j);
            float pj = __shfl_sync(FULL, p, j);
            if (tj == t) { psum += pj; firstl = min(firstl, j); }
        }
        int tkeep = (firstl == lane) ? t : -1;

        // publish for the other 7 chunk blocks of this row
        g_tgt[base]   = tkeep;
        g_probs[base] = psum;
        __threadfence();
        if (lane == 0) atomicExch(&g_flag[row], 1);

        // scatter targets that land in chunk 0 (zeroing done by warps 1..7,
        // ordered by the __syncthreads below)
        __syncthreads();
        if (tkeep >= 0 && tkeep < CHUNK_F) rowp[tkeep] = psum;
        return;
    }

    // ================= zeroing (all blocks; chunk0: threads 32..255) =======
    if (chunk == 0) {
        for (int i = tid - 32; i < CHUNK_F4; i += 224) rowp4[i] = z;
        __syncthreads();   // pairs with warp0's barrier above
        return;
    }

    #pragma unroll
    for (int i = tid; i < CHUNK_F4; i += 256) rowp4[i] = z;
    __syncthreads();       // order zero stores before the scatter stores

    if (tid < 32) {
        // acquire the row's scatter list
        if (lane == 0) {
            while (atomicAdd(&g_flag[row], 0) == 0) { __nanosleep(64); }
        }
        __syncwarp();
        __threadfence();
        int   t = g_tgt  [row * KK + lane];
        float p = g_probs[row * KK + lane];
        int loc = t - lo;
        if (loc >= 0 && loc < CHUNK_F) rowp[loc] = p;   // t == -1 never hits
    }
}

// metadata order:
//  0 tgt_index(i32) 1 knn_dists 2 knn_key_feature 3 network_probs(UNUSED)
//  4 network_select_probs 5 dfc_w(UNUSED) 6 dfc_b(UNUSED)
//  7 fc1_w1 8 fc1_b1 9 fc1_w2 10 fc1_b2 11 fc2_w1 12 fc2_b1 13 fc2_w2 14 fc2_b2
extern "C" void kernel_launch(void* const* d_in, const int* in_sizes, int n_in,
                              void* d_out, int out_size) {
    const int*   tgt    = (const int*)  d_in[0];
    const float* dists  = (const float*)d_in[1];
    const float* kkf    = (const float*)d_in[2];
    const float* nsp    = (const float*)d_in[4];
    const float* fc1_w1 = (const float*)d_in[7];
    const float* fc1_b1 = (const float*)d_in[8];
    const float* fc1_w2 = (const float*)d_in[9];
    const float* fc1_b2 = (const float*)d_in[10];
    const float* fc2_w1 = (const float*)d_in[11];
    const float* fc2_b1 = (const float*)d_in[12];
    const float* fc2_w2 = (const float*)d_in[13];
    const float* fc2_b2 = (const float*)d_in[14];
    float* out = (float*)d_out;

    dim3 grid(NCHUNK, ROWS);
    fused_kernel<<<grid, 256>>>(tgt, dists, kkf, nsp,
                                fc1_w1, fc1_b1, fc1_w2, fc1_b2,
                                fc2_w1, fc2_b1, fc2_w2, fc2_b2,
                                out);
}

// round 6
// speedup vs baseline: 1.4370x; 1.4370x over previous
#include <cuda_runtime.h>
#include <cstdint>

// Problem constants (B=4, S=1024, K=32, V=32000)
#define BB 4
#define SS 1024
#define KK 32
#define VV 32000
#define ROWS (BB * SS)          // 4096
#define CHUNK 1024              // floats per zero-block (256 threads * float4)
#define NCHUNK ((VV + CHUNK - 1) / CHUNK)   // 32 (last chunk = 256 floats)

// Scratch (device global — no allocation). Per-(row,k) softmax probs.
__device__ float g_probs[ROWS * KK];

__device__ __forceinline__ float fast_tanh(float x) {
    float r;
    asm("tanh.approx.f32 %0, %1;" : "=f"(r) : "f"(x));
    return r;
}

// ---------------------------------------------------------------------------
// Kernel A: one warp per row, 8 rows per block. Minimal-chain version:
//  - label counts via match_any + ballot + popc (no shuffle loops)
//  - fc2 feats staged in shared memory (LDS broadcast instead of shuffles)
//  - no dedup pass (kernel B uses atomicAdd)
// ---------------------------------------------------------------------------
__global__ void __launch_bounds__(256) compute_kernel(
    const int*   __restrict__ tgt,
    const float* __restrict__ dists,
    const float* __restrict__ kkf,
    const float* __restrict__ nsp,
    const float* __restrict__ fc1_w1,  // (2,4)
    const float* __restrict__ fc1_b1,  // (4)
    const float* __restrict__ fc1_w2,  // (4,1)
    const float* __restrict__ fc1_b2,  // (1)
    const float* __restrict__ fc2_w1,  // (64,32)
    const float* __restrict__ fc2_b1,  // (32)
    const float* __restrict__ fc2_w2,  // (32,2)
    const float* __restrict__ fc2_b2)  // (2)
{
    const unsigned FULL = 0xffffffffu;
    __shared__ float feat[8][64];

    const int w    = threadIdx.x >> 5;
    const int lane = threadIdx.x & 31;
    const int row  = blockIdx.x * 8 + w;
    const int base = row * KK + lane;

    int   t   = tgt[base];
    float d   = dists[base];
    float lkf = __logf(kkf[base]);
    float lsp = __logf(nsp[base]);

    // ---- label_counts: distinct nonzero labels in prefix [0..lane] --------
    unsigned mgrp = __match_any_sync(FULL, t);
    bool fo = (t != 0) && ((mgrp & (0u - mgrp)) == (1u << lane)); // lowest lane of group
    unsigned fomask = __ballot_sync(FULL, fo);
    float lc = (float)__popc(fomask & (0xFFFFFFFFu >> (31 - lane)));

    // ---- fc1 -> noise_logit ------------------------------------------------
    float noise = fc1_b2[0];
    #pragma unroll
    for (int m = 0; m < 4; m++) {
        float h = fmaf(lkf, fc1_w1[m], fmaf(lsp, fc1_w1[4 + m], fc1_b1[m]));
        noise = fmaf(fast_tanh(h), fc1_w2[m], noise);
    }

    // ---- stage feats for fc2 ----------------------------------------------
    feat[w][lane]      = d;
    feat[w][32 + lane] = lc;
    __syncwarp();

    // ---- fc2: hidden[lane] = b1[lane] + sum_j feat[j]*W1[j][lane] ---------
    // LDS broadcast + L1-hot LDG; all 64 iterations independent.
    float hid = fc2_b1[lane];
    #pragma unroll
    for (int j = 0; j < 64; j++) {
        hid = fmaf(feat[w][j], fc2_w1[j * 32 + lane], hid);
    }
    float ht = fast_tanh(hid);

    // ---- lambda_logit[1] -> tempe ------------------------------------------
    float l1 = ht * fc2_w2[lane * 2 + 1];
    #pragma unroll
    for (int off = 16; off; off >>= 1) l1 += __shfl_xor_sync(FULL, l1, off);
    l1 += fc2_b2[1];
    float tempe = 1.f / (1.f + __expf(-l1));

    // ---- softmax over K of (-d*tempe + noise) ------------------------------
    float logit = fmaf(-d, tempe, noise);
    float mx = logit;
    #pragma unroll
    for (int off = 16; off; off >>= 1) mx = fmaxf(mx, __shfl_xor_sync(FULL, mx, off));
    float e = __expf(logit - mx);
    float s = e;
    #pragma unroll
    for (int off = 16; off; off >>= 1) s += __shfl_xor_sync(FULL, s, off);

    g_probs[base] = e / s;
}

// ---------------------------------------------------------------------------
// Kernel B: zero + inline scatter (proven 73.4us shape from R4).
// One block per 1024-float chunk of one row; 1 float4 store per thread.
// After zeroing, warp 0 atomicAdds any of the row's 32 targets that fall in
// this chunk (atomics absorb duplicate targets).
// ---------------------------------------------------------------------------
__global__ void __launch_bounds__(256) zero_scatter_kernel(
    const int* __restrict__ tgt,
    float*     __restrict__ out)
{
    const int row   = blockIdx.y;
    const int chunk = blockIdx.x;
    const int tid   = threadIdx.x;

    const int lo = chunk * CHUNK;
    const int n  = min(CHUNK, VV - lo);          // 1024, or 256 for last chunk
    float* rowp = out + (size_t)row * VV + lo;

    // prefetch the scatter list (warp 0) before the stores
    int   t = -1;
    float p = 0.f;
    if (tid < 32) {
        t = tgt[row * KK + tid];
        p = g_probs[row * KK + tid];
    }

    // zero this chunk: one float4 per thread
    int i4 = tid * 4;
    if (i4 < n) *(float4*)(rowp + i4) = make_float4(0.f, 0.f, 0.f, 0.f);

    __syncthreads();  // order zero-stores before the targeted adds

    if (tid < 32) {
        int loc = t - lo;
        if (loc >= 0 && loc < n) atomicAdd(rowp + loc, p);
    }
}

// metadata order:
//  0 tgt_index(i32) 1 knn_dists 2 knn_key_feature 3 network_probs(UNUSED)
//  4 network_select_probs 5 dfc_w(UNUSED) 6 dfc_b(UNUSED)
//  7 fc1_w1 8 fc1_b1 9 fc1_w2 10 fc1_b2 11 fc2_w1 12 fc2_b1 13 fc2_w2 14 fc2_b2
extern "C" void kernel_launch(void* const* d_in, const int* in_sizes, int n_in,
                              void* d_out, int out_size) {
    const int*   tgt    = (const int*)  d_in[0];
    const float* dists  = (const float*)d_in[1];
    const float* kkf    = (const float*)d_in[2];
    const float* nsp    = (const float*)d_in[4];
    const float* fc1_w1 = (const float*)d_in[7];
    const float* fc1_b1 = (const float*)d_in[8];
    const float* fc1_w2 = (const float*)d_in[9];
    const float* fc1_b2 = (const float*)d_in[10];
    const float* fc2_w1 = (const float*)d_in[11];
    const float* fc2_b1 = (const float*)d_in[12];
    const float* fc2_w2 = (const float*)d_in[13];
    const float* fc2_b2 = (const float*)d_in[14];
    float* out = (float*)d_out;

    // A: 4096 rows, 8 rows/block -> 512 blocks
    compute_kernel<<<ROWS / 8, 256>>>(tgt, dists, kkf, nsp,
                                      fc1_w1, fc1_b1, fc1_w2, fc1_b2,
                                      fc2_w1, fc2_b1, fc2_w2, fc2_b2);

    // B: flat zero+scatter, grid (32 chunks, 4096 rows)
    dim3 grid(NCHUNK, ROWS);
    zero_scatter_kernel<<<grid, 256>>>(tgt, out);
}